// round 5
// baseline (speedup 1.0000x reference)
#include <cuda_runtime.h>
#include <math.h>

#define NMAX   50000
#define EMAX   800000
#define ERELMX 200000
#define H      2
#define D      32
#define HD     64
#define INF_   64
#define DREL   32

// ---------------- scratch (device globals; no allocation allowed) ----------
__device__ __align__(16) float    g_hp  [NMAX * HD];     // target projection [N,H*D]
__device__ __align__(16) float    g_esrc[NMAX * H];      // per-node src logit
__device__ __align__(16) float    g_edst[NMAX * H];      // per-node dst logit
__device__ __align__(16) float    g_Gmid[NMAX * HD];     // midp @ W_edge_top  [N,H,D]
__device__ __align__(16) float    g_amid[NMAX * H];      // attn_edge·relu(midp)
__device__ __align__(16) float    g_Grel[ERELMX * HD];   // relp @ W_edge_bot  [EREL,H,D]
__device__ __align__(16) float    g_arel[ERELMX * H];    // attn_edge·relu(relp)
__device__ __align__(16) float    g_e   [EMAX * H];      // per-edge logits
__device__ __align__(16) unsigned g_m   [NMAX * H];      // segment max (order-encoded)
__device__ __align__(16) float    g_den [NMAX * H];      // softmax denominator
__device__ __align__(16) float    g_acc [NMAX * HD];     // aggregated numerator

// ---------------- helpers --------------------------------------------------
__device__ __forceinline__ unsigned fenc(float f) {
    unsigned u = __float_as_uint(f);
    return (u & 0x80000000u) ? ~u : (u | 0x80000000u);
}
__device__ __forceinline__ float fdec(unsigned u) {
    return (u & 0x80000000u) ? __uint_as_float(u & 0x7fffffffu)
                             : __uint_as_float(~u);
}
__device__ __forceinline__ float halfred(float v) {   // sum over 16-lane half
    v += __shfl_xor_sync(0xffffffffu, v, 8);
    v += __shfl_xor_sync(0xffffffffu, v, 4);
    v += __shfl_xor_sync(0xffffffffu, v, 2);
    v += __shfl_xor_sync(0xffffffffu, v, 1);
    return v;
}

// ---------------- init scratch --------------------------------------------
__global__ void k_init(int N) {
    int i      = blockIdx.x * blockDim.x + threadIdx.x;
    int stride = gridDim.x * blockDim.x;
    for (int k = i; k < N * H;  k += stride) { g_m[k] = 0u; g_den[k] = 0.f; }
    for (int k = i; k < N * HD; k += stride) { g_acc[k] = 0.f; }
}

// ---------------- K1: target node projection + per-node logits -------------
__global__ void k_node(const float* __restrict__ h,  const float* __restrict__ Wt,
                       const float* __restrict__ bt, const float* __restrict__ asrc,
                       const float* __restrict__ adst, int N) {
    __shared__ float Ws[INF_ * HD];                    // 16KB
    for (int i = threadIdx.x; i < INF_ * HD; i += blockDim.x) Ws[i] = Wt[i];
    __syncthreads();
    int lane = threadIdx.x & 31;
    int w    = (blockIdx.x * blockDim.x + threadIdx.x) >> 5;
    int nw   = (gridDim.x * blockDim.x) >> 5;
    int j    = 2 * lane;
    int hh   = lane >> 4;
    float b0  = bt[j],   b1  = bt[j + 1];
    float as0 = asrc[j], as1 = asrc[j + 1];
    float ad0 = adst[j], ad1 = adst[j + 1];
    for (int n = w; n < N; n += nw) {
        float2 x = *(const float2*)(h + (size_t)n * INF_ + j);
        float a0 = b0, a1 = b1;
#pragma unroll
        for (int k = 0; k < INF_; k++) {
            float xk = __shfl_sync(0xffffffffu, (k & 1) ? x.y : x.x, k >> 1);
            float2 wv = *(const float2*)(Ws + k * HD + j);
            a0 = fmaf(xk, wv.x, a0);
            a1 = fmaf(xk, wv.y, a1);
        }
        *(float2*)(g_hp + (size_t)n * HD + j) = make_float2(a0, a1);
        float r0 = fmaxf(a0, 0.f), r1 = fmaxf(a1, 0.f);
        float ps = halfred(as0 * r0 + as1 * r1);
        float pd = halfred(ad0 * r0 + ad1 * r1);
        if ((lane & 15) == 0) {
            g_esrc[n * H + hh] = ps;
            g_edst[n * H + hh] = pd;
        }
    }
}

// ---------------- K2: mid projection -> amid, Gmid --------------------------
__global__ void k_mid(const float* __restrict__ nf, const float* __restrict__ Wm,
                      const float* __restrict__ bm, const float* __restrict__ aedge,
                      const float* __restrict__ We, int N) {
    __shared__ float Ws[INF_ * HD];                    // 16KB
    __shared__ float Es[HD * D];                       // 8KB (W_edge 64x32)
    for (int i = threadIdx.x; i < INF_ * HD; i += blockDim.x) Ws[i] = Wm[i];
    for (int i = threadIdx.x; i < HD * D;   i += blockDim.x) Es[i] = We[i];
    __syncthreads();
    int lane = threadIdx.x & 31;
    int w    = (blockIdx.x * blockDim.x + threadIdx.x) >> 5;
    int nw   = (gridDim.x * blockDim.x) >> 5;
    int j    = 2 * lane;
    int hh   = lane >> 4;
    int dj   = 2 * (lane & 15);
    float b0  = bm[j], b1 = bm[j + 1];
    float ae0 = aedge[hh * 64 + dj], ae1 = aedge[hh * 64 + dj + 1];
    for (int n = w; n < N; n += nw) {
        float2 x = *(const float2*)(nf + (size_t)n * INF_ + j);
        float a0 = b0, a1 = b1;
#pragma unroll
        for (int k = 0; k < INF_; k++) {
            float xk = __shfl_sync(0xffffffffu, (k & 1) ? x.y : x.x, k >> 1);
            float2 wv = *(const float2*)(Ws + k * HD + j);
            a0 = fmaf(xk, wv.x, a0);
            a1 = fmaf(xk, wv.y, a1);
        }
        float pa = halfred(ae0 * fmaxf(a0, 0.f) + ae1 * fmaxf(a1, 0.f));
        if ((lane & 15) == 0) g_amid[n * H + hh] = pa;
        float g0 = 0.f, g1 = 0.f;
#pragma unroll
        for (int d = 0; d < D; d++) {
            float v = __shfl_sync(0xffffffffu, (d & 1) ? a1 : a0,
                                  (lane & 16) + (d >> 1));
            float2 wv = *(const float2*)(Es + d * D + dj);
            g0 = fmaf(v, wv.x, g0);
            g1 = fmaf(v, wv.y, g1);
        }
        *(float2*)(g_Gmid + (size_t)n * HD + j) = make_float2(g0, g1);
    }
}

// ---------------- K3: rel projection -> arel, Grel --------------------------
__global__ void k_rel(const float* __restrict__ ef, const float* __restrict__ Wr,
                      const float* __restrict__ br, const float* __restrict__ aedge,
                      const float* __restrict__ We, int NR) {
    __shared__ float Ws[DREL * HD];                    // 8KB
    __shared__ float Es[HD * D];                       // 8KB
    for (int i = threadIdx.x; i < DREL * HD; i += blockDim.x) Ws[i] = Wr[i];
    for (int i = threadIdx.x; i < HD * D;   i += blockDim.x) Es[i] = We[i];
    __syncthreads();
    int lane = threadIdx.x & 31;
    int w    = (blockIdx.x * blockDim.x + threadIdx.x) >> 5;
    int nw   = (gridDim.x * blockDim.x) >> 5;
    int j    = 2 * lane;
    int hh   = lane >> 4;
    int dj   = 2 * (lane & 15);
    float b0  = br[j], b1 = br[j + 1];
    float ae0 = aedge[hh * 64 + 32 + dj], ae1 = aedge[hh * 64 + 32 + dj + 1];
    for (int r = w; r < NR; r += nw) {
        float x = ef[(size_t)r * DREL + lane];
        float a0 = b0, a1 = b1;
#pragma unroll
        for (int k = 0; k < DREL; k++) {
            float xk = __shfl_sync(0xffffffffu, x, k);
            float2 wv = *(const float2*)(Ws + k * HD + j);
            a0 = fmaf(xk, wv.x, a0);
            a1 = fmaf(xk, wv.y, a1);
        }
        float pa = halfred(ae0 * fmaxf(a0, 0.f) + ae1 * fmaxf(a1, 0.f));
        if ((lane & 15) == 0) g_arel[r * H + hh] = pa;
        float g0 = 0.f, g1 = 0.f;
#pragma unroll
        for (int d = 0; d < D; d++) {
            float v = __shfl_sync(0xffffffffu, (d & 1) ? a1 : a0,
                                  (lane & 16) + (d >> 1));
            float2 wv = *(const float2*)(Es + (32 + d) * D + dj);
            g0 = fmaf(v, wv.x, g0);
            g1 = fmaf(v, wv.y, g1);
        }
        *(float2*)(g_Grel + (size_t)r * HD + j) = make_float2(g0, g1);
    }
}

// ---------------- Pass A: edge logits + segment max -------------------------
__global__ void k_edges_a(const int* __restrict__ src, const int* __restrict__ dst,
                          const int* __restrict__ hn,  const int* __restrict__ he,
                          int E) {
    int e = blockIdx.x * blockDim.x + threadIdx.x;
    if (e >= E) return;
    int s = src[e], d = dst[e], n = hn[e], r = he[e];
    float2 es = *(const float2*)(g_esrc + s * 2);
    float2 ed = *(const float2*)(g_edst + d * 2);
    float2 am = *(const float2*)(g_amid + n * 2);
    float2 ar = *(const float2*)(g_arel + r * 2);
    float e0 = es.x + ed.x + am.x + ar.x;
    float e1 = es.y + ed.y + am.y + ar.y;
    *(float2*)(g_e + (size_t)e * 2) = make_float2(e0, e1);
    atomicMax(&g_m[d * 2],     fenc(e0));
    atomicMax(&g_m[d * 2 + 1], fenc(e1));
}

// ---------------- Pass B: exp + fused aggregation (warp per edge) ----------
__global__ void k_edges_b(const int* __restrict__ src, const int* __restrict__ dst,
                          const int* __restrict__ hn,  const int* __restrict__ he,
                          int E) {
    int lane = threadIdx.x & 31;
    int w    = (blockIdx.x * blockDim.x + threadIdx.x) >> 5;
    if (w >= E) return;
    int s = src[w], d = dst[w], n = hn[w], r = he[w];
    float2 ev = *(const float2*)(g_e + (size_t)w * 2);
    float m0 = fdec(g_m[d * 2]);
    float m1 = fdec(g_m[d * 2 + 1]);
    float ex0 = exp2f((ev.x - m0) * 1.4426950408889634f);
    float ex1 = exp2f((ev.y - m1) * 1.4426950408889634f);
    if (lane < 2) atomicAdd(&g_den[d * 2 + lane], lane ? ex1 : ex0);
    int j = 2 * lane;
    float2 a = *(const float2*)(g_hp   + (size_t)s * HD + j);
    float2 b = *(const float2*)(g_Gmid + (size_t)n * HD + j);
    float2 c = *(const float2*)(g_Grel + (size_t)r * HD + j);
    float exh = (lane >= 16) ? ex1 : ex0;
    float2 v = make_float2((a.x + b.x + c.x) * exh,
                           (a.y + b.y + c.y) * exh);
    atomicAdd((float2*)(g_acc + (size_t)d * HD + j), v);   // RED.64, sm_90+
}

// ---------------- Finalize: bias + residual + relu + L2 norm ---------------
__global__ void k_final(const float* __restrict__ bedge, float* __restrict__ out,
                        int N) {
    int lane = threadIdx.x & 31;
    int w    = (blockIdx.x * blockDim.x + threadIdx.x) >> 5;
    if (w >= N) return;
    float2 dn = *(const float2*)(g_den + w * 2);
    float inv0 = dn.x > 0.f ? 1.f / dn.x : 0.f;
    float inv1 = dn.y > 0.f ? 1.f / dn.y : 0.f;
    int j  = 2 * lane;
    int dj = 2 * (lane & 15);
    float2 ac = *(const float2*)(g_acc + (size_t)w * HD + j);
    float2 hv = *(const float2*)(g_hp  + (size_t)w * HD + j);
    float invh = (lane >= 16) ? inv1 : inv0;
    float v0 = fmaxf(ac.x * invh + bedge[dj]     + hv.x, 0.f);
    float v1 = fmaxf(ac.y * invh + bedge[dj + 1] + hv.y, 0.f);
    float ss = v0 * v0 + v1 * v1;
    ss += __shfl_xor_sync(0xffffffffu, ss, 16);
    ss += __shfl_xor_sync(0xffffffffu, ss, 8);
    ss += __shfl_xor_sync(0xffffffffu, ss, 4);
    ss += __shfl_xor_sync(0xffffffffu, ss, 2);
    ss += __shfl_xor_sync(0xffffffffu, ss, 1);
    float sc = 1.f / fmaxf(sqrtf(ss), 1e-12f);
    *(float2*)(out + (size_t)w * HD + j) = make_float2(v0 * sc, v1 * sc);
}

// ---------------- launch ----------------------------------------------------
extern "C" void kernel_launch(void* const* d_in, const int* in_sizes, int n_in,
                              void* d_out, int out_size) {
    const float* h         = (const float*)d_in[0];
    const float* W_t       = (const float*)d_in[1];
    const float* b_t       = (const float*)d_in[2];
    const float* nfeat_mid = (const float*)d_in[3];
    const float* W_mid     = (const float*)d_in[4];
    const float* b_mid     = (const float*)d_in[5];
    const float* efeat_rel = (const float*)d_in[6];
    const float* W_rel     = (const float*)d_in[7];
    const float* b_rel     = (const float*)d_in[8];
    const float* attn_src  = (const float*)d_in[9];
    const float* attn_dst  = (const float*)d_in[10];
    const float* attn_edge = (const float*)d_in[11];
    const float* W_edge    = (const float*)d_in[12];
    const float* b_edge    = (const float*)d_in[13];
    const int*   src       = (const int*)d_in[14];
    const int*   dst       = (const int*)d_in[15];
    const int*   hn        = (const int*)d_in[16];
    const int*   he        = (const int*)d_in[17];

    int N    = in_sizes[0]  / INF_;
    int E    = in_sizes[14];
    int EREL = in_sizes[6]  / DREL;

    k_init<<<256, 256>>>(N);
    k_node<<<592, 256>>>(h, W_t, b_t, attn_src, attn_dst, N);
    k_mid <<<592, 256>>>(nfeat_mid, W_mid, b_mid, attn_edge, W_edge, N);
    k_rel <<<592, 256>>>(efeat_rel, W_rel, b_rel, attn_edge, W_edge, EREL);
    k_edges_a<<<(E + 255) / 256, 256>>>(src, dst, hn, he, E);
    {
        long long threads = (long long)E * 32;
        int blocks = (int)((threads + 255) / 256);
        k_edges_b<<<blocks, 256>>>(src, dst, hn, he, E);
    }
    {
        long long threads = (long long)N * 32;
        int blocks = (int)((threads + 255) / 256);
        k_final<<<blocks, 256>>>(b_edge, (float*)d_out, N);
    }
}

// round 16
// speedup vs baseline: 1.6019x; 1.6019x over previous
#include <cuda_runtime.h>
#include <math.h>

#define NMAX   50000
#define EMAX   800000
#define ERELMX 200000
#define H      2
#define D      32
#define HD     64
#define INF_   64
#define DREL   32

// ---------------- scratch (device globals; no allocation allowed) ----------
__device__ __align__(16) float    g_hp  [NMAX * HD];     // target projection [N,H*D]
__device__ __align__(16) float    g_esrc[NMAX * H];      // per-node src logit
__device__ __align__(16) float    g_edst[NMAX * H];      // per-node dst logit
__device__ __align__(16) float    g_Gmid[NMAX * HD];     // midp @ W_edge_top  [N,H,D]
__device__ __align__(16) float    g_amid[NMAX * H];      // attn_edge·relu(midp)
__device__ __align__(16) float    g_Grel[ERELMX * HD];   // relp @ W_edge_bot  [EREL,H,D]
__device__ __align__(16) float    g_arel[ERELMX * H];    // attn_edge·relu(relp)
__device__ __align__(16) float    g_e   [EMAX * H];      // per-edge logits
__device__ __align__(16) unsigned g_m   [NMAX * H];      // segment max (order-encoded)
__device__ __align__(16) float    g_den [NMAX * H];      // softmax denominator
__device__ __align__(16) float    g_acc [NMAX * HD];     // aggregated numerator

// ---------------- helpers --------------------------------------------------
__device__ __forceinline__ unsigned fenc(float f) {
    unsigned u = __float_as_uint(f);
    return (u & 0x80000000u) ? ~u : (u | 0x80000000u);
}
__device__ __forceinline__ float fdec(unsigned u) {
    return (u & 0x80000000u) ? __uint_as_float(u & 0x7fffffffu)
                             : __uint_as_float(~u);
}
__device__ __forceinline__ float halfred(float v) {   // sum over 16-lane half
    v += __shfl_xor_sync(0xffffffffu, v, 8);
    v += __shfl_xor_sync(0xffffffffu, v, 4);
    v += __shfl_xor_sync(0xffffffffu, v, 2);
    v += __shfl_xor_sync(0xffffffffu, v, 1);
    return v;
}
__device__ __forceinline__ float f4c(const float4& v, int c) { // static comp pick
    return c == 0 ? v.x : c == 1 ? v.y : c == 2 ? v.z : v.w;
}

// ---------------- init scratch --------------------------------------------
__global__ void k_init(int N) {
    int i      = blockIdx.x * blockDim.x + threadIdx.x;
    int stride = gridDim.x * blockDim.x;
    for (int k = i; k < N * H;  k += stride) { g_m[k] = 0u; g_den[k] = 0.f; }
    for (int k = i; k < N * HD; k += stride) { g_acc[k] = 0.f; }
}

// ---------------- K1: target node projection + per-node logits -------------
// 4 rows per warp: one weight LDS.64 feeds 8 FMAs.
__global__ void k_node(const float* __restrict__ h,  const float* __restrict__ Wt,
                       const float* __restrict__ bt, const float* __restrict__ asrc,
                       const float* __restrict__ adst, int N) {
    __shared__ float Ws[INF_ * HD];                    // 16KB
    for (int i = threadIdx.x; i < INF_ * HD; i += blockDim.x) Ws[i] = Wt[i];
    __syncthreads();
    int lane = threadIdx.x & 31;
    int w    = (blockIdx.x * blockDim.x + threadIdx.x) >> 5;
    int nw   = (gridDim.x * blockDim.x) >> 5;
    int j    = 2 * lane;
    int hh   = lane >> 4;
    float b0  = bt[j],   b1  = bt[j + 1];
    float as0 = asrc[j], as1 = asrc[j + 1];
    float ad0 = adst[j], ad1 = adst[j + 1];
    for (int r4 = w * 4; r4 < N; r4 += nw * 4) {
        if (r4 + 4 <= N) {
            float4 xa = *(const float4*)(h + (size_t)r4 * INF_ + 4 * lane);
            float4 xb = *(const float4*)(h + (size_t)r4 * INF_ + 128 + 4 * lane);
            float a0[4] = {b0, b0, b0, b0};
            float a1[4] = {b1, b1, b1, b1};
#pragma unroll
            for (int k = 0; k < INF_; k++) {
                float2 wv = *(const float2*)(Ws + k * HD + j);
                float sa = f4c(xa, k & 3), sb = f4c(xb, k & 3);
                int sl = k >> 2;
                float x0 = __shfl_sync(0xffffffffu, sa, sl);
                float x1 = __shfl_sync(0xffffffffu, sa, 16 + sl);
                float x2 = __shfl_sync(0xffffffffu, sb, sl);
                float x3 = __shfl_sync(0xffffffffu, sb, 16 + sl);
                a0[0] = fmaf(x0, wv.x, a0[0]); a1[0] = fmaf(x0, wv.y, a1[0]);
                a0[1] = fmaf(x1, wv.x, a0[1]); a1[1] = fmaf(x1, wv.y, a1[1]);
                a0[2] = fmaf(x2, wv.x, a0[2]); a1[2] = fmaf(x2, wv.y, a1[2]);
                a0[3] = fmaf(x3, wv.x, a0[3]); a1[3] = fmaf(x3, wv.y, a1[3]);
            }
#pragma unroll
            for (int i = 0; i < 4; i++) {
                *(float2*)(g_hp + (size_t)(r4 + i) * HD + j) = make_float2(a0[i], a1[i]);
                float r0 = fmaxf(a0[i], 0.f), r1 = fmaxf(a1[i], 0.f);
                float ps = halfred(as0 * r0 + as1 * r1);
                float pd = halfred(ad0 * r0 + ad1 * r1);
                if ((lane & 15) == 0) {
                    g_esrc[(r4 + i) * H + hh] = ps;
                    g_edst[(r4 + i) * H + hh] = pd;
                }
            }
        } else {                                        // remainder rows
            for (int n = r4; n < N; n++) {
                float2 x = *(const float2*)(h + (size_t)n * INF_ + j);
                float a0 = b0, a1 = b1;
#pragma unroll
                for (int k = 0; k < INF_; k++) {
                    float xk = __shfl_sync(0xffffffffu, (k & 1) ? x.y : x.x, k >> 1);
                    float2 wv = *(const float2*)(Ws + k * HD + j);
                    a0 = fmaf(xk, wv.x, a0);
                    a1 = fmaf(xk, wv.y, a1);
                }
                *(float2*)(g_hp + (size_t)n * HD + j) = make_float2(a0, a1);
                float r0 = fmaxf(a0, 0.f), r1 = fmaxf(a1, 0.f);
                float ps = halfred(as0 * r0 + as1 * r1);
                float pd = halfred(ad0 * r0 + ad1 * r1);
                if ((lane & 15) == 0) {
                    g_esrc[n * H + hh] = ps;
                    g_edst[n * H + hh] = pd;
                }
            }
        }
    }
}

// ---------------- K2: mid projection -> amid, Gmid --------------------------
__global__ void k_mid(const float* __restrict__ nf, const float* __restrict__ Wm,
                      const float* __restrict__ bm, const float* __restrict__ aedge,
                      const float* __restrict__ We, int N) {
    __shared__ float Ws[INF_ * HD];                    // 16KB
    __shared__ float Es[HD * D];                       // 8KB (W_edge 64x32)
    for (int i = threadIdx.x; i < INF_ * HD; i += blockDim.x) Ws[i] = Wm[i];
    for (int i = threadIdx.x; i < HD * D;   i += blockDim.x) Es[i] = We[i];
    __syncthreads();
    int lane = threadIdx.x & 31;
    int w    = (blockIdx.x * blockDim.x + threadIdx.x) >> 5;
    int nw   = (gridDim.x * blockDim.x) >> 5;
    int j    = 2 * lane;
    int hh   = lane >> 4;
    int dj   = 2 * (lane & 15);
    float b0  = bm[j], b1 = bm[j + 1];
    float ae0 = aedge[hh * 64 + dj], ae1 = aedge[hh * 64 + dj + 1];
    for (int r4 = w * 4; r4 < N; r4 += nw * 4) {
        if (r4 + 4 <= N) {
            float4 xa = *(const float4*)(nf + (size_t)r4 * INF_ + 4 * lane);
            float4 xb = *(const float4*)(nf + (size_t)r4 * INF_ + 128 + 4 * lane);
            float a0[4] = {b0, b0, b0, b0};
            float a1[4] = {b1, b1, b1, b1};
#pragma unroll
            for (int k = 0; k < INF_; k++) {
                float2 wv = *(const float2*)(Ws + k * HD + j);
                float sa = f4c(xa, k & 3), sb = f4c(xb, k & 3);
                int sl = k >> 2;
                float x0 = __shfl_sync(0xffffffffu, sa, sl);
                float x1 = __shfl_sync(0xffffffffu, sa, 16 + sl);
                float x2 = __shfl_sync(0xffffffffu, sb, sl);
                float x3 = __shfl_sync(0xffffffffu, sb, 16 + sl);
                a0[0] = fmaf(x0, wv.x, a0[0]); a1[0] = fmaf(x0, wv.y, a1[0]);
                a0[1] = fmaf(x1, wv.x, a0[1]); a1[1] = fmaf(x1, wv.y, a1[1]);
                a0[2] = fmaf(x2, wv.x, a0[2]); a1[2] = fmaf(x2, wv.y, a1[2]);
                a0[3] = fmaf(x3, wv.x, a0[3]); a1[3] = fmaf(x3, wv.y, a1[3]);
            }
#pragma unroll
            for (int i = 0; i < 4; i++) {
                float pa = halfred(ae0 * fmaxf(a0[i], 0.f) + ae1 * fmaxf(a1[i], 0.f));
                if ((lane & 15) == 0) g_amid[(r4 + i) * H + hh] = pa;
            }
            float g0[4] = {0.f, 0.f, 0.f, 0.f};
            float g1[4] = {0.f, 0.f, 0.f, 0.f};
#pragma unroll
            for (int d = 0; d < D; d++) {
                float2 wv = *(const float2*)(Es + d * D + dj);
#pragma unroll
                for (int i = 0; i < 4; i++) {
                    float v = __shfl_sync(0xffffffffu, (d & 1) ? a1[i] : a0[i],
                                          (lane & 16) + (d >> 1));
                    g0[i] = fmaf(v, wv.x, g0[i]);
                    g1[i] = fmaf(v, wv.y, g1[i]);
                }
            }
#pragma unroll
            for (int i = 0; i < 4; i++)
                *(float2*)(g_Gmid + (size_t)(r4 + i) * HD + j) = make_float2(g0[i], g1[i]);
        } else {
            for (int n = r4; n < N; n++) {
                float2 x = *(const float2*)(nf + (size_t)n * INF_ + j);
                float a0 = b0, a1 = b1;
#pragma unroll
                for (int k = 0; k < INF_; k++) {
                    float xk = __shfl_sync(0xffffffffu, (k & 1) ? x.y : x.x, k >> 1);
                    float2 wv = *(const float2*)(Ws + k * HD + j);
                    a0 = fmaf(xk, wv.x, a0);
                    a1 = fmaf(xk, wv.y, a1);
                }
                float pa = halfred(ae0 * fmaxf(a0, 0.f) + ae1 * fmaxf(a1, 0.f));
                if ((lane & 15) == 0) g_amid[n * H + hh] = pa;
                float g0 = 0.f, g1 = 0.f;
#pragma unroll
                for (int d = 0; d < D; d++) {
                    float v = __shfl_sync(0xffffffffu, (d & 1) ? a1 : a0,
                                          (lane & 16) + (d >> 1));
                    float2 wv = *(const float2*)(Es + d * D + dj);
                    g0 = fmaf(v, wv.x, g0);
                    g1 = fmaf(v, wv.y, g1);
                }
                *(float2*)(g_Gmid + (size_t)n * HD + j) = make_float2(g0, g1);
            }
        }
    }
}

// ---------------- K3: rel projection -> arel, Grel --------------------------
__global__ void k_rel(const float* __restrict__ ef, const float* __restrict__ Wr,
                      const float* __restrict__ br, const float* __restrict__ aedge,
                      const float* __restrict__ We, int NR) {
    __shared__ float Ws[DREL * HD];                    // 8KB
    __shared__ float Es[HD * D];                       // 8KB
    for (int i = threadIdx.x; i < DREL * HD; i += blockDim.x) Ws[i] = Wr[i];
    for (int i = threadIdx.x; i < HD * D;   i += blockDim.x) Es[i] = We[i];
    __syncthreads();
    int lane = threadIdx.x & 31;
    int w    = (blockIdx.x * blockDim.x + threadIdx.x) >> 5;
    int nw   = (gridDim.x * blockDim.x) >> 5;
    int j    = 2 * lane;
    int hh   = lane >> 4;
    int dj   = 2 * (lane & 15);
    float b0  = br[j], b1 = br[j + 1];
    float ae0 = aedge[hh * 64 + 32 + dj], ae1 = aedge[hh * 64 + 32 + dj + 1];
    for (int r4 = w * 4; r4 < NR; r4 += nw * 4) {
        if (r4 + 4 <= NR) {
            float4 x = *(const float4*)(ef + (size_t)r4 * DREL + 4 * lane);
            float a0[4] = {b0, b0, b0, b0};
            float a1[4] = {b1, b1, b1, b1};
#pragma unroll
            for (int k = 0; k < DREL; k++) {
                float2 wv = *(const float2*)(Ws + k * HD + j);
                float s = f4c(x, k & 3);
                int sl = k >> 2;
                float x0 = __shfl_sync(0xffffffffu, s, sl);
                float x1 = __shfl_sync(0xffffffffu, s, 8 + sl);
                float x2 = __shfl_sync(0xffffffffu, s, 16 + sl);
                float x3 = __shfl_sync(0xffffffffu, s, 24 + sl);
                a0[0] = fmaf(x0, wv.x, a0[0]); a1[0] = fmaf(x0, wv.y, a1[0]);
                a0[1] = fmaf(x1, wv.x, a0[1]); a1[1] = fmaf(x1, wv.y, a1[1]);
                a0[2] = fmaf(x2, wv.x, a0[2]); a1[2] = fmaf(x2, wv.y, a1[2]);
                a0[3] = fmaf(x3, wv.x, a0[3]); a1[3] = fmaf(x3, wv.y, a1[3]);
            }
#pragma unroll
            for (int i = 0; i < 4; i++) {
                float pa = halfred(ae0 * fmaxf(a0[i], 0.f) + ae1 * fmaxf(a1[i], 0.f));
                if ((lane & 15) == 0) g_arel[(r4 + i) * H + hh] = pa;
            }
            float g0[4] = {0.f, 0.f, 0.f, 0.f};
            float g1[4] = {0.f, 0.f, 0.f, 0.f};
#pragma unroll
            for (int d = 0; d < D; d++) {
                float2 wv = *(const float2*)(Es + (32 + d) * D + dj);
#pragma unroll
                for (int i = 0; i < 4; i++) {
                    float v = __shfl_sync(0xffffffffu, (d & 1) ? a1[i] : a0[i],
                                          (lane & 16) + (d >> 1));
                    g0[i] = fmaf(v, wv.x, g0[i]);
                    g1[i] = fmaf(v, wv.y, g1[i]);
                }
            }
#pragma unroll
            for (int i = 0; i < 4; i++)
                *(float2*)(g_Grel + (size_t)(r4 + i) * HD + j) = make_float2(g0[i], g1[i]);
        } else {
            for (int r = r4; r < NR; r++) {
                float xv = ef[(size_t)r * DREL + lane];
                float a0 = b0, a1 = b1;
#pragma unroll
                for (int k = 0; k < DREL; k++) {
                    float xk = __shfl_sync(0xffffffffu, xv, k);
                    float2 wv = *(const float2*)(Ws + k * HD + j);
                    a0 = fmaf(xk, wv.x, a0);
                    a1 = fmaf(xk, wv.y, a1);
                }
                float pa = halfred(ae0 * fmaxf(a0, 0.f) + ae1 * fmaxf(a1, 0.f));
                if ((lane & 15) == 0) g_arel[r * H + hh] = pa;
                float g0 = 0.f, g1 = 0.f;
#pragma unroll
                for (int d = 0; d < D; d++) {
                    float v = __shfl_sync(0xffffffffu, (d & 1) ? a1 : a0,
                                          (lane & 16) + (d >> 1));
                    float2 wv = *(const float2*)(Es + (32 + d) * D + dj);
                    g0 = fmaf(v, wv.x, g0);
                    g1 = fmaf(v, wv.y, g1);
                }
                *(float2*)(g_Grel + (size_t)r * HD + j) = make_float2(g0, g1);
            }
        }
    }
}

// ---------------- Pass A: edge logits + segment max -------------------------
__global__ void k_edges_a(const int* __restrict__ src, const int* __restrict__ dst,
                          const int* __restrict__ hn,  const int* __restrict__ he,
                          int E) {
    int e = blockIdx.x * blockDim.x + threadIdx.x;
    if (e >= E) return;
    int s = src[e], d = dst[e], n = hn[e], r = he[e];
    float2 es = *(const float2*)(g_esrc + s * 2);
    float2 ed = *(const float2*)(g_edst + d * 2);
    float2 am = *(const float2*)(g_amid + n * 2);
    float2 ar = *(const float2*)(g_arel + r * 2);
    float e0 = es.x + ed.x + am.x + ar.x;
    float e1 = es.y + ed.y + am.y + ar.y;
    *(float2*)(g_e + (size_t)e * 2) = make_float2(e0, e1);
    atomicMax(&g_m[d * 2],     fenc(e0));
    atomicMax(&g_m[d * 2 + 1], fenc(e1));
}

// ---------------- Pass B: exp + fused aggregation (16 lanes per edge) -------
// Each 16-lane group owns one edge; lane covers 4 consecutive floats (float4).
// Head boundary (col 32) falls at sub-lane 8, so the float4 never straddles it.
__global__ void k_edges_b(const int* __restrict__ src, const int* __restrict__ dst,
                          const int* __restrict__ hn,  const int* __restrict__ he,
                          int E) {
    int tid = blockIdx.x * blockDim.x + threadIdx.x;
    int e   = tid >> 4;
    if (e >= E) return;
    int sub = threadIdx.x & 15;
    int s = src[e], d = dst[e], n = hn[e], r = he[e];
    float2 ev = *(const float2*)(g_e + (size_t)e * 2);
    float m0 = fdec(g_m[d * 2]);
    float m1 = fdec(g_m[d * 2 + 1]);
    float ex0 = exp2f((ev.x - m0) * 1.4426950408889634f);
    float ex1 = exp2f((ev.y - m1) * 1.4426950408889634f);
    if (sub == 0) atomicAdd(&g_den[d * 2],     ex0);
    if (sub == 8) atomicAdd(&g_den[d * 2 + 1], ex1);
    int j = 4 * sub;
    float4 a = *(const float4*)(g_hp   + (size_t)s * HD + j);
    float4 b = *(const float4*)(g_Gmid + (size_t)n * HD + j);
    float4 c = *(const float4*)(g_Grel + (size_t)r * HD + j);
    float exh = (sub >= 8) ? ex1 : ex0;
    float4 v = make_float4((a.x + b.x + c.x) * exh,
                           (a.y + b.y + c.y) * exh,
                           (a.z + b.z + c.z) * exh,
                           (a.w + b.w + c.w) * exh);
    atomicAdd((float4*)(g_acc + (size_t)d * HD + j), v);   // RED.128, sm_90+
}

// ---------------- Finalize: bias + residual + relu + L2 norm ---------------
__global__ void k_final(const float* __restrict__ bedge, float* __restrict__ out,
                        int N) {
    int lane = threadIdx.x & 31;
    int w    = (blockIdx.x * blockDim.x + threadIdx.x) >> 5;
    if (w >= N) return;
    float2 dn = *(const float2*)(g_den + w * 2);
    float inv0 = dn.x > 0.f ? 1.f / dn.x : 0.f;
    float inv1 = dn.y > 0.f ? 1.f / dn.y : 0.f;
    int j  = 2 * lane;
    int dj = 2 * (lane & 15);
    float2 ac = *(const float2*)(g_acc + (size_t)w * HD + j);
    float2 hv = *(const float2*)(g_hp  + (size_t)w * HD + j);
    float invh = (lane >= 16) ? inv1 : inv0;
    float v0 = fmaxf(ac.x * invh + bedge[dj]     + hv.x, 0.f);
    float v1 = fmaxf(ac.y * invh + bedge[dj + 1] + hv.y, 0.f);
    float ss = v0 * v0 + v1 * v1;
    ss += __shfl_xor_sync(0xffffffffu, ss, 16);
    ss += __shfl_xor_sync(0xffffffffu, ss, 8);
    ss += __shfl_xor_sync(0xffffffffu, ss, 4);
    ss += __shfl_xor_sync(0xffffffffu, ss, 2);
    ss += __shfl_xor_sync(0xffffffffu, ss, 1);
    float sc = 1.f / fmaxf(sqrtf(ss), 1e-12f);
    *(float2*)(out + (size_t)w * HD + j) = make_float2(v0 * sc, v1 * sc);
}

// ---------------- launch ----------------------------------------------------
extern "C" void kernel_launch(void* const* d_in, const int* in_sizes, int n_in,
                              void* d_out, int out_size) {
    const float* h         = (const float*)d_in[0];
    const float* W_t       = (const float*)d_in[1];
    const float* b_t       = (const float*)d_in[2];
    const float* nfeat_mid = (const float*)d_in[3];
    const float* W_mid     = (const float*)d_in[4];
    const float* b_mid     = (const float*)d_in[5];
    const float* efeat_rel = (const float*)d_in[6];
    const float* W_rel     = (const float*)d_in[7];
    const float* b_rel     = (const float*)d_in[8];
    const float* attn_src  = (const float*)d_in[9];
    const float* attn_dst  = (const float*)d_in[10];
    const float* attn_edge = (const float*)d_in[11];
    const float* W_edge    = (const float*)d_in[12];
    const float* b_edge    = (const float*)d_in[13];
    const int*   src       = (const int*)d_in[14];
    const int*   dst       = (const int*)d_in[15];
    const int*   hn        = (const int*)d_in[16];
    const int*   he        = (const int*)d_in[17];

    int N    = in_sizes[0]  / INF_;
    int E    = in_sizes[14];
    int EREL = in_sizes[6]  / DREL;

    k_init<<<256, 256>>>(N);
    k_node<<<592, 256>>>(h, W_t, b_t, attn_src, attn_dst, N);
    k_mid <<<592, 256>>>(nfeat_mid, W_mid, b_mid, attn_edge, W_edge, N);
    k_rel <<<592, 256>>>(efeat_rel, W_rel, b_rel, attn_edge, W_edge, EREL);
    k_edges_a<<<(E + 255) / 256, 256>>>(src, dst, hn, he, E);
    {
        long long threads = (long long)E * 16;
        int blocks = (int)((threads + 255) / 256);
        k_edges_b<<<blocks, 256>>>(src, dst, hn, he, E);
    }
    {
        long long threads = (long long)N * 32;
        int blocks = (int)((threads + 255) / 256);
        k_final<<<blocks, 256>>>(b_edge, (float*)d_out, N);
    }
}